// round 12
// baseline (speedup 1.0000x reference)
#include <cuda_runtime.h>
#include <cstdint>

// Problem constants (LangevinSDEContiformer: B=1024, S=512, H=64, D_IN=3)
#define BB   1024
#define SS   512
#define HH   64
#define DIN  3
#define SM1  511    // S-1 steps

__device__ float d_sigsc[SM1 * HH];
__device__ float d_hstep[SM1];
__device__ float d_times[SM1];

__global__ void sigma_kernel(const float* __restrict__ ts,
                             const float* __restrict__ Wd1, const float* __restrict__ bd1,
                             const float* __restrict__ Wd2, const float* __restrict__ bd2,
                             const float* __restrict__ minp, const float* __restrict__ maxp)
{
    __shared__ float hh[32];
    int s = blockIdx.x;
    int tid = threadIdx.x;
    float t = ts[(size_t)s * DIN];
    if (tid < 32) hh[tid] = fmaxf(t * Wd1[tid] + bd1[tid], 0.0f);
    __syncthreads();
    float acc = bd2[tid];
    #pragma unroll
    for (int i = 0; i < 32; i++) acc += hh[i] * Wd2[i * HH + tid];
    float sp = fmaxf(acc, 0.0f) + log1pf(expf(-fabsf(acc)));
    float mind = fabsf(minp[0]);
    float maxd = fabsf(maxp[0]);
    float sig = fminf(fmaxf(sp + mind, mind), maxd);
    float hs = ts[(size_t)(s + 1) * DIN] - t;
    d_sigsc[s * HH + tid] = sig * sqrtf(hs);
    if (tid == 0) { d_hstep[s] = hs; d_times[s] = t; }
}

// ---------------------------------------------------------------------------
// f32x2 helpers
// ---------------------------------------------------------------------------
typedef unsigned long long u64;

__device__ __forceinline__ void fma2(u64& acc, u64 a, u64 b) {
    asm("fma.rn.f32x2 %0, %1, %2, %0;" : "+l"(acc) : "l"(a), "l"(b));
}
__device__ __forceinline__ float fold2(u64 p) {
    unsigned int lo, hi;
    asm("mov.b64 {%0, %1}, %2;" : "=r"(lo), "=r"(hi) : "l"(p));
    return __uint_as_float(lo) + __uint_as_float(hi);
}
__device__ __forceinline__ u64 pk2(float lo, float hi) {
    u64 r;
    asm("mov.b64 %0, {%1, %2};" : "=l"(r) : "r"(__float_as_uint(lo)), "r"(__float_as_uint(hi)));
    return r;
}
__device__ __forceinline__ float tanh_fast(float x) {
    float y;
    asm("tanh.approx.f32 %0, %1;" : "=f"(y) : "f"(x));
    return y;
}

// ---------------------------------------------------------------------------
// Shared layout. 128 CTAs x 256 thr; 2 groups x (4 warps, 4 rows).
// k-split-4 per group; combines fused into consumer-warp prologues (R11 winner).
// Weights stored as PRE-PAIRED f32x2 (u64) -> LDS.64 gives FMA2 operand with
// NO unpack ALU.  4 layouts (fwd/bwd for W1/W2), 4096 u64 each = 128 KB.
// ---------------------------------------------------------------------------
#define PB_STRIDE 65
// u64 region (offsets in u64 units)
#define OFF_WF1   0                      // [32][128] pairs along k (W1 fwd)
#define OFF_WF2   (OFF_WF1 + 4096)       // [64][64]  pairs along k (W2 fwd)
#define OFF_WF2T  (OFF_WF2 + 4096)       // [32][128] pairs along j (W2^T bwd)
#define OFF_WF1T  (OFF_WF2T + 4096)      // [64][64]  pairs along i (W1^T bwd)
#define U64_WORDS (OFF_WF1T + 4096)      // 16384 u64 = 131072 B
// f32 region (offsets in f32 units, starting after u64 region)
#define OFF_W1T   (U64_WORDS * 2)        // [128] f32 t-row of W1
#define OFF_B1    (OFF_W1T + 128)        // [128]
#define OFF_B2    (OFF_B1 + 128)         // [64]
#define OFF_W3    (OFF_B2 + 64)          // [64]
#define OFF_Y     (OFF_W3 + 64)          // [8][64] f32
#define OFF_H1    (OFF_Y + 512)          // [8][128] f32
#define OFF_G2    (OFF_H1 + 1024)        // [8][64] f32
#define OFF_G1    (OFF_G2 + 512)         // [8][128] f32
#define OFF_PA    (OFF_G1 + 1024)        // 4096 f32
#define OFF_PB    (OFF_PA + 4096)        // 32*65 = 2080 f32
#define SMEM_FLOATS (OFF_PB + 2080 + 16)
#define SMEM_BYTES  (SMEM_FLOATS * 4)    // ~170 KB (fits 227KB, occupancy 1)

__global__ void __launch_bounds__(256, 1)
sde_scan_kernel(const float* __restrict__ ts, const float* __restrict__ noise,
                const float* __restrict__ Wp1, const float* __restrict__ bp1,
                const float* __restrict__ Wp2, const float* __restrict__ bp2,
                const float* __restrict__ Wp3, float* __restrict__ out)
{
    extern __shared__ float smf[];
    u64* Wf1  = (u64*)smf + OFF_WF1;
    u64* Wf2  = (u64*)smf + OFF_WF2;
    u64* Wf2t = (u64*)smf + OFF_WF2T;
    u64* Wf1t = (u64*)smf + OFF_WF1T;
    float* W1t = smf + OFF_W1T;
    float* B1s = smf + OFF_B1;
    float* B2s = smf + OFF_B2;
    float* W3s = smf + OFF_W3;
    float* Y   = smf + OFF_Y;
    float* H1s = smf + OFF_H1;
    float* G2s = smf + OFF_G2;
    float* G1s = smf + OFF_G1;
    float* PA  = smf + OFF_PA;
    float* PB  = smf + OFF_PB;

    const int tid  = threadIdx.x;
    const int lane = tid & 31;
    const int wid  = tid >> 5;
    const int g    = wid >> 2;           // row group 0/1 (4 rows each)
    const int p    = wid & 3;            // split parity 0..3
    const int rbase = g * 4;
    const int rowTop = blockIdx.x * 8;
    const int barid = g + 1;             // per-group named barrier (128 thr)

    const int l16  = lane & 15;          // sub-lane for 16-wide chunks
    const int rA   = lane >> 4;          // row 0/1 (and +2) for 16-wide chunks

    // ---- pack weights into shared as f32x2 pairs (4 layouts)
    for (int i = tid; i < 4096; i += 256) {           // Wf1[k2][j]
        int k2 = i >> 7, j = i & 127;
        Wf1[i] = pk2(Wp1[(2 * k2) * 128 + j], Wp1[(2 * k2 + 1) * 128 + j]);
    }
    for (int i = tid; i < 4096; i += 256) {           // Wf2[k2][j]
        int k2 = i >> 6, j = i & 63;
        Wf2[i] = pk2(Wp2[(2 * k2) * 64 + j], Wp2[(2 * k2 + 1) * 64 + j]);
    }
    for (int i = tid; i < 4096; i += 256) {           // Wf2t[j2][i]
        int j2 = i >> 7, ii = i & 127;
        Wf2t[i] = pk2(Wp2[ii * 64 + 2 * j2], Wp2[ii * 64 + 2 * j2 + 1]);
    }
    for (int i = tid; i < 4096; i += 256) {           // Wf1t[i2][kout]
        int i2 = i >> 6, ko = i & 63;
        Wf1t[i] = pk2(Wp1[ko * 128 + 2 * i2], Wp1[ko * 128 + 2 * i2 + 1]);
    }
    if (tid < 128) { W1t[tid] = Wp1[64 * 128 + tid]; B1s[tid] = bp1[tid]; }
    if (tid < 64)  { B2s[tid] = bp2[tid]; W3s[tid] = Wp3[tid]; }

    // ---- init y0 and write out[:,0,:]
    #pragma unroll
    for (int q = 0; q < 2; q++) {
        int e = q * 256 + tid;
        int k = e & 63, r8 = e >> 6;
        int b = rowTop + r8;
        float v = (k < DIN) ? ts[(size_t)b * SS * DIN + k] : 0.0f;
        Y[r8 * 64 + k] = v;
        out[((size_t)b * SS) * HH + k] = v;
    }
    __syncthreads();

    for (int s = 0; s < SM1; s++) {
        const float tcur  = d_times[s];
        const float hstep = d_hstep[s];

        // prefetch noise*sigma for THIS warp's ynew chunk:
        //   k = p*16 + l16, rows rbase + rA and rbase + rA + 2
        const int kz = p * 16 + l16;
        float zsc[2];
        #pragma unroll
        for (int q = 0; q < 2; q++) {
            int r = rA + 2 * q;
            int b = rowTop + rbase + r;
            zsc[q] = d_sigsc[s * HH + kz] * noise[((size_t)s * BB + b) * HH + kz];
        }

        // ===== P1 matmul: [y,t] @ W1 partials; own k-chunk [p*16,p*16+16) ===
        {
            u64 acc[4][4];
            #pragma unroll
            for (int r = 0; r < 4; r++)
                #pragma unroll
                for (int m = 0; m < 4; m++) acc[r][m] = 0ull;
            #pragma unroll
            for (int n = 0; n < 8; n++) {
                const int k2 = p * 8 + n;             // k pair
                u64 av[4];
                #pragma unroll
                for (int r = 0; r < 4; r++)
                    av[r] = *(const u64*)&Y[(rbase + r) * 64 + 2 * k2];
                u64 wp[4];
                #pragma unroll
                for (int m = 0; m < 4; m++)
                    wp[m] = Wf1[k2 * 128 + lane + 32 * m];
                #pragma unroll
                for (int r = 0; r < 4; r++)
                    #pragma unroll
                    for (int m = 0; m < 4; m++) fma2(acc[r][m], av[r], wp[m]);
            }
            #pragma unroll
            for (int r = 0; r < 4; r++)
                #pragma unroll
                for (int m = 0; m < 4; m++)
                    PA[((g * 4 + p) * 4 + r) * 128 + lane + 32 * m] = fold2(acc[r][m]);
        }
        asm volatile("bar.sync %0, %1;" :: "r"(barid), "r"(128) : "memory");

        // ===== P2 prologue (fused combine): h1 for own k-chunk [p*32,+32) ===
        {
            const int j = p * 32 + lane;
            #pragma unroll
            for (int r = 0; r < 4; r++) {
                float sum = (PA[((g * 4 + 0) * 4 + r) * 128 + j]
                           + PA[((g * 4 + 1) * 4 + r) * 128 + j])
                          + (PA[((g * 4 + 2) * 4 + r) * 128 + j]
                           + PA[((g * 4 + 3) * 4 + r) * 128 + j]);
                H1s[(rbase + r) * 128 + j] = tanh_fast(sum + fmaf(tcur, W1t[j], B1s[j]));
            }
        }
        __syncwarp();
        // ===== P2 matmul: h1 @ W2 partials; own k-chunk [p*32,+32) ==========
        {
            u64 acc[4][2];
            #pragma unroll
            for (int r = 0; r < 4; r++) { acc[r][0] = 0ull; acc[r][1] = 0ull; }
            #pragma unroll
            for (int n = 0; n < 16; n++) {
                const int k2 = p * 16 + n;
                u64 av[4];
                #pragma unroll
                for (int r = 0; r < 4; r++)
                    av[r] = *(const u64*)&H1s[(rbase + r) * 128 + 2 * k2];
                u64 wp[2];
                #pragma unroll
                for (int m = 0; m < 2; m++)
                    wp[m] = Wf2[k2 * 64 + lane + 32 * m];
                #pragma unroll
                for (int r = 0; r < 4; r++)
                    #pragma unroll
                    for (int m = 0; m < 2; m++) fma2(acc[r][m], av[r], wp[m]);
            }
            #pragma unroll
            for (int r = 0; r < 4; r++)
                #pragma unroll
                for (int m = 0; m < 2; m++)
                    PB[((g * 4 + p) * 4 + r) * PB_STRIDE + lane + 32 * m] = fold2(acc[r][m]);
        }
        asm volatile("bar.sync %0, %1;" :: "r"(barid), "r"(128) : "memory");

        // ===== P3 prologue (fused combine): g2 for own j-chunk [p*16,+16) ===
        {
            const int j = p * 16 + l16;
            #pragma unroll
            for (int q = 0; q < 2; q++) {
                int r = rA + 2 * q;
                float sum = (PB[((g * 4 + 0) * 4 + r) * PB_STRIDE + j]
                           + PB[((g * 4 + 1) * 4 + r) * PB_STRIDE + j])
                          + (PB[((g * 4 + 2) * 4 + r) * PB_STRIDE + j]
                           + PB[((g * 4 + 3) * 4 + r) * PB_STRIDE + j]);
                float h2 = tanh_fast(sum + B2s[j]);
                G2s[(rbase + r) * 64 + j] = W3s[j] * (1.0f - h2 * h2);
            }
        }
        __syncwarp();
        // ===== P3 matmul: g2 @ W2^T partials; own j-chunk [p*16,+16) ========
        {
            u64 acc[4][4];
            #pragma unroll
            for (int r = 0; r < 4; r++)
                #pragma unroll
                for (int m = 0; m < 4; m++) acc[r][m] = 0ull;
            #pragma unroll
            for (int n = 0; n < 8; n++) {
                const int j2 = p * 8 + n;
                u64 av[4];
                #pragma unroll
                for (int r = 0; r < 4; r++)
                    av[r] = *(const u64*)&G2s[(rbase + r) * 64 + 2 * j2];
                u64 wp[4];
                #pragma unroll
                for (int m = 0; m < 4; m++)
                    wp[m] = Wf2t[j2 * 128 + lane + 32 * m];
                #pragma unroll
                for (int r = 0; r < 4; r++)
                    #pragma unroll
                    for (int m = 0; m < 4; m++) fma2(acc[r][m], av[r], wp[m]);
            }
            #pragma unroll
            for (int r = 0; r < 4; r++)
                #pragma unroll
                for (int m = 0; m < 4; m++)
                    PA[((g * 4 + p) * 4 + r) * 128 + lane + 32 * m] = fold2(acc[r][m]);
        }
        asm volatile("bar.sync %0, %1;" :: "r"(barid), "r"(128) : "memory");

        // ===== P4 prologue (fused combine): g1 for own i-chunk [p*32,+32) ===
        {
            const int i = p * 32 + lane;
            #pragma unroll
            for (int r = 0; r < 4; r++) {
                float sum = (PA[((g * 4 + 0) * 4 + r) * 128 + i]
                           + PA[((g * 4 + 1) * 4 + r) * 128 + i])
                          + (PA[((g * 4 + 2) * 4 + r) * 128 + i]
                           + PA[((g * 4 + 3) * 4 + r) * 128 + i]);
                float h1v = H1s[(rbase + r) * 128 + i];
                G1s[(rbase + r) * 128 + i] = sum * (1.0f - h1v * h1v);
            }
        }
        __syncwarp();
        // ===== P4 matmul: g1 @ W1^T partials; own i-chunk [p*32,+32) ========
        {
            u64 acc[4][2];
            #pragma unroll
            for (int r = 0; r < 4; r++) { acc[r][0] = 0ull; acc[r][1] = 0ull; }
            #pragma unroll
            for (int n = 0; n < 16; n++) {
                const int i2 = p * 16 + n;
                u64 av[4];
                #pragma unroll
                for (int r = 0; r < 4; r++)
                    av[r] = *(const u64*)&G1s[(rbase + r) * 128 + 2 * i2];
                u64 wp[2];
                #pragma unroll
                for (int m = 0; m < 2; m++)
                    wp[m] = Wf1t[i2 * 64 + lane + 32 * m];
                #pragma unroll
                for (int r = 0; r < 4; r++)
                    #pragma unroll
                    for (int m = 0; m < 2; m++) fma2(acc[r][m], av[r], wp[m]);
            }
            #pragma unroll
            for (int r = 0; r < 4; r++)
                #pragma unroll
                for (int m = 0; m < 2; m++)
                    PB[((g * 4 + p) * 4 + r) * PB_STRIDE + lane + 32 * m] = fold2(acc[r][m]);
        }
        asm volatile("bar.sync %0, %1;" :: "r"(barid), "r"(128) : "memory");

        // ===== step tail (fused combine): ynew for own k-chunk [p*16,+16) ===
        // next P1 reads only this warp's Y chunk -> __syncwarp suffices.
        {
            #pragma unroll
            for (int q = 0; q < 2; q++) {
                int r = rA + 2 * q;
                float dy = (PB[((g * 4 + 0) * 4 + r) * PB_STRIDE + kz]
                          + PB[((g * 4 + 1) * 4 + r) * PB_STRIDE + kz])
                         + (PB[((g * 4 + 2) * 4 + r) * PB_STRIDE + kz]
                          + PB[((g * 4 + 3) * 4 + r) * PB_STRIDE + kz]);
                int r8 = rbase + r;
                int b = rowTop + r8;
                float ynew = fmaf(-dy, hstep, Y[r8 * 64 + kz]) + zsc[q];
                Y[r8 * 64 + kz] = ynew;
                out[((size_t)b * SS + (s + 1)) * HH + kz] = ynew;
            }
        }
        __syncwarp();
    }
}

// ---------------------------------------------------------------------------
extern "C" void kernel_launch(void* const* d_in, const int* in_sizes, int n_in,
                              void* d_out, int out_size)
{
    (void)in_sizes; (void)n_in; (void)out_size;
    const float* ts    = (const float*)d_in[0];   // time_series (B,S,3)
    const float* noise = (const float*)d_in[1];   // (S-1,B,H)
    const float* Wp1   = (const float*)d_in[2];   // (65,128)
    const float* bp1   = (const float*)d_in[3];   // (128,)
    const float* Wp2   = (const float*)d_in[4];   // (128,64)
    const float* bp2   = (const float*)d_in[5];   // (64,)
    const float* Wp3   = (const float*)d_in[6];   // (64,1)
    // d_in[7] = bp3 (unused: constant shift, zero gradient)
    const float* Wd1   = (const float*)d_in[8];   // (1,32)
    const float* bd1   = (const float*)d_in[9];   // (32,)
    const float* Wd2   = (const float*)d_in[10];  // (32,64)
    const float* bd2   = (const float*)d_in[11];  // (64,)
    const float* mn    = (const float*)d_in[12];  // scalar
    const float* mx    = (const float*)d_in[13];  // scalar
    float* out = (float*)d_out;

    cudaFuncSetAttribute(sde_scan_kernel,
                         cudaFuncAttributeMaxDynamicSharedMemorySize, SMEM_BYTES);

    sigma_kernel<<<SM1, HH>>>(ts, Wd1, bd1, Wd2, bd2, mn, mx);
    sde_scan_kernel<<<BB / 8, 256, SMEM_BYTES>>>(ts, noise, Wp1, bp1, Wp2, bp2, Wp3, out);
}

// round 13
// speedup vs baseline: 1.1693x; 1.1693x over previous
#include <cuda_runtime.h>
#include <cuda_bf16.h>
#include <mma.h>
#include <cstdint>

using namespace nvcuda;

// Problem constants (LangevinSDEContiformer: B=1024, S=512, H=64, D_IN=3)
#define BB   1024
#define SS   512
#define HH   64
#define DIN  3
#define SM1  511    // S-1 steps

__device__ float d_sigsc[SM1 * HH];
__device__ float d_hstep[SM1];
__device__ float d_times[SM1];

__global__ void sigma_kernel(const float* __restrict__ ts,
                             const float* __restrict__ Wd1, const float* __restrict__ bd1,
                             const float* __restrict__ Wd2, const float* __restrict__ bd2,
                             const float* __restrict__ minp, const float* __restrict__ maxp)
{
    __shared__ float hh[32];
    int s = blockIdx.x;
    int tid = threadIdx.x;
    float t = ts[(size_t)s * DIN];
    if (tid < 32) hh[tid] = fmaxf(t * Wd1[tid] + bd1[tid], 0.0f);
    __syncthreads();
    float acc = bd2[tid];
    #pragma unroll
    for (int i = 0; i < 32; i++) acc += hh[i] * Wd2[i * HH + tid];
    float sp = fmaxf(acc, 0.0f) + log1pf(expf(-fabsf(acc)));
    float mind = fabsf(minp[0]);
    float maxd = fabsf(maxp[0]);
    float sig = fminf(fmaxf(sp + mind, mind), maxd);
    float hs = ts[(size_t)(s + 1) * DIN] - t;
    d_sigsc[s * HH + tid] = sig * sqrtf(hs);
    if (tid == 0) { d_hstep[s] = hs; d_times[s] = t; }
}

__device__ __forceinline__ float tanh_fast(float x) {
    float y;
    asm("tanh.approx.f32 %0, %1;" : "=f"(y) : "f"(x));
    return y;
}

// ---------------------------------------------------------------------------
// Tensor-core scan kernel. 128 CTAs x 256 thr (8 warps). 8 batch rows/CTA.
// All 4 matmul phases use wmma m8n32k16 (bf16 in, f32 acc): M=8 rows exact.
//   128-col phases (P1,P3): 8 warps = 4 n-tiles(32) x 2 k-halves   (K=64)
//    64-col phases (P2,P4): 8 warps = 2 n-tiles(32) x 4 k-quarters (K=128)
// Partial C tiles -> per-warp smem scratch; epilogue by the producing
// pair/quad after a LOCAL named barrier; full __syncthreads only between
// phases (4 per step).  State y stays fp32; activations bf16.
// ---------------------------------------------------------------------------
// bf16 element offsets
#define LDW1  136     // W1s / W2Ts row stride (128 cols + 8 pad)
#define LDW2  72      // W2s / W1Ts row stride (64 cols + 8 pad)
#define LDA   72      // Ybf / G2bf stride (64 + 8)
#define LDH   136     // H1bf / G1bf stride (128 + 8)
#define OFF_W1S   0                       // [64][136]
#define OFF_W2S   (OFF_W1S  + 64*136)     // [128][72]
#define OFF_W2TS  (OFF_W2S  + 128*72)     // [64][136]
#define OFF_W1TS  (OFF_W2TS + 64*136)     // [128][72]
#define OFF_YBF   (OFF_W1TS + 128*72)     // [8][72]
#define OFF_H1BF  (OFF_YBF  + 8*72)       // [8][136]
#define OFF_G2BF  (OFF_H1BF + 8*136)      // [8][72]
#define OFF_G1BF  (OFF_G2BF + 8*72)       // [8][136]
#define BF16_ELEMS (OFF_G1BF + 8*136)     // 39168 (even)
// f32 offsets (units of f32, from smem base)
#define F32_BASE  (BF16_ELEMS / 2)        // 19584
#define OFF_W1T   (F32_BASE)              // [128]
#define OFF_B1    (OFF_W1T + 128)         // [128]
#define OFF_B2    (OFF_B1 + 128)          // [64]
#define OFF_W3    (OFF_B2 + 64)           // [64]
#define OFF_YF    (OFF_W3 + 64)           // [8][64]
#define OFF_CS    (OFF_YF + 512)          // 8 warps x [8][40] = 2560
#define SMEM_FLOATS (OFF_CS + 2560)
#define SMEM_BYTES  (SMEM_FLOATS * 4)     // ~92 KB

#define LDC 40        // C scratch row stride (f32)

__global__ void __launch_bounds__(256, 1)
sde_scan_kernel(const float* __restrict__ ts, const float* __restrict__ noise,
                const float* __restrict__ Wp1, const float* __restrict__ bp1,
                const float* __restrict__ Wp2, const float* __restrict__ bp2,
                const float* __restrict__ Wp3, float* __restrict__ out)
{
    extern __shared__ float smf[];
    __nv_bfloat16* bfb  = (__nv_bfloat16*)smf;
    __nv_bfloat16* W1s  = bfb + OFF_W1S;   // [64][136]  W1[k][j]
    __nv_bfloat16* W2s  = bfb + OFF_W2S;   // [128][72]  W2[k][j]
    __nv_bfloat16* W2Ts = bfb + OFF_W2TS;  // [64][136]  W2T[j][i] = W2[i][j]
    __nv_bfloat16* W1Ts = bfb + OFF_W1TS;  // [128][72]  W1T[i][k] = W1[k][i]
    __nv_bfloat16* Ybf  = bfb + OFF_YBF;   // [8][72]
    __nv_bfloat16* H1bf = bfb + OFF_H1BF;  // [8][136]
    __nv_bfloat16* G2bf = bfb + OFF_G2BF;  // [8][72]
    __nv_bfloat16* G1bf = bfb + OFF_G1BF;  // [8][136]
    float* W1t = smf + OFF_W1T;
    float* B1s = smf + OFF_B1;
    float* B2s = smf + OFF_B2;
    float* W3s = smf + OFF_W3;
    float* Yf  = smf + OFF_YF;             // fp32 master state [8][64]
    float* CSf = smf + OFF_CS;             // per-warp C scratch [8][8][40]

    const int tid  = threadIdx.x;
    const int lane = tid & 31;
    const int w    = tid >> 5;            // warp 0..7
    const int pp   = w >> 1;              // pair 0..3 (128-col phases)
    const int kh   = w & 1;               // k-half
    const int qq   = w >> 2;              // quad 0..1 (64-col phases)
    const int kq   = w & 3;               // k-quarter
    const int t64  = tid & 63;            // id within pair
    const int t128 = tid & 127;           // id within quad
    const int rowTop = blockIdx.x * 8;

    // ---- pack weights (bf16, 4 layouts) + consts
    for (int i = tid; i < 64 * 128; i += 256) {        // W1s[k][j]
        int k = i >> 7, j = i & 127;
        W1s[k * LDW1 + j] = __float2bfloat16(Wp1[i]);
    }
    for (int i = tid; i < 128 * 64; i += 256) {        // W2s[k][j]
        int k = i >> 6, j = i & 63;
        W2s[k * LDW2 + j] = __float2bfloat16(Wp2[i]);
    }
    for (int i = tid; i < 64 * 128; i += 256) {        // W2Ts[j][i2]
        int j = i >> 7, i2 = i & 127;
        W2Ts[j * LDW1 + i2] = __float2bfloat16(Wp2[i2 * 64 + j]);
    }
    for (int i = tid; i < 128 * 64; i += 256) {        // W1Ts[i2][k]
        int i2 = i >> 6, k = i & 63;
        W1Ts[i2 * LDW2 + k] = __float2bfloat16(Wp1[k * 128 + i2]);
    }
    if (tid < 128) { W1t[tid] = Wp1[64 * 128 + tid]; B1s[tid] = bp1[tid]; }
    if (tid < 64)  { B2s[tid] = bp2[tid]; W3s[tid] = Wp3[tid]; }

    // ---- init y0 (fp32 master + bf16 copy) and write out[:,0,:]
    #pragma unroll
    for (int q = 0; q < 2; q++) {
        int e = q * 256 + tid;
        int k = e & 63, r = e >> 6;
        int b = rowTop + r;
        float v = (k < DIN) ? ts[(size_t)b * SS * DIN + k] : 0.0f;
        Yf[r * 64 + k] = v;
        Ybf[r * LDA + k] = __float2bfloat16(v);
        out[((size_t)b * SS) * HH + k] = v;
    }
    __syncthreads();

    wmma::fragment<wmma::matrix_a, 8, 32, 16, __nv_bfloat16, wmma::row_major> fa;
    wmma::fragment<wmma::matrix_b, 8, 32, 16, __nv_bfloat16, wmma::row_major> fb;
    wmma::fragment<wmma::accumulator, 8, 32, 16, float> fc;

    float* CSw = CSf + w * 320;            // this warp's C tile [8][40]

    for (int s = 0; s < SM1; s++) {
        const float tcur  = d_times[s];
        const float hstep = d_hstep[s];

        // prefetch noise*sigma matching E4's (r, k) assignment
        float zsc[2];
        #pragma unroll
        for (int q = 0; q < 2; q++) {
            int e = q * 128 + t128;
            int r = e >> 5, k = qq * 32 + (e & 31);
            int b = rowTop + r;
            zsc[q] = d_sigsc[s * HH + k] * noise[((size_t)s * BB + b) * HH + k];
        }

        // ===== P1: [y] @ W1  (8x128, K=64): nt=pp, khalf=kh =================
        wmma::fill_fragment(fc, 0.0f);
        #pragma unroll
        for (int u = 0; u < 2; u++) {
            int kt = kh * 2 + u;
            wmma::load_matrix_sync(fa, Ybf + kt * 16, LDA);
            wmma::load_matrix_sync(fb, W1s + (kt * 16) * LDW1 + pp * 32, LDW1);
            wmma::mma_sync(fc, fa, fb, fc);
        }
        wmma::store_matrix_sync(CSw, fc, LDC, wmma::mem_row_major);
        asm volatile("bar.sync %0, %1;" :: "r"(1 + pp), "r"(64) : "memory");
        // E1 (pair): h1 = tanh(sum2 + t*W1t + b1) -> H1bf
        {
            const float* c0 = CSf + (2 * pp) * 320;
            const float* c1 = CSf + (2 * pp + 1) * 320;
            #pragma unroll
            for (int q = 0; q < 4; q++) {
                int e = q * 64 + t64;
                int r = e >> 5, cl = e & 31, c = pp * 32 + cl;
                float v = c0[r * LDC + cl] + c1[r * LDC + cl]
                        + fmaf(tcur, W1t[c], B1s[c]);
                H1bf[r * LDH + c] = __float2bfloat16(tanh_fast(v));
            }
        }
        __syncthreads();

        // ===== P2: h1 @ W2  (8x64, K=128): nt=qq, kquarter=kq ===============
        wmma::fill_fragment(fc, 0.0f);
        #pragma unroll
        for (int u = 0; u < 2; u++) {
            int kt = kq * 2 + u;
            wmma::load_matrix_sync(fa, H1bf + kt * 16, LDH);
            wmma::load_matrix_sync(fb, W2s + (kt * 16) * LDW2 + qq * 32, LDW2);
            wmma::mma_sync(fc, fa, fb, fc);
        }
        wmma::store_matrix_sync(CSw, fc, LDC, wmma::mem_row_major);
        asm volatile("bar.sync %0, %1;" :: "r"(5 + qq), "r"(128) : "memory");
        // E2 (quad): g2 = W3*(1 - tanh(sum4 + b2)^2) -> G2bf
        {
            const float* cb = CSf + (qq * 4) * 320;
            #pragma unroll
            for (int q = 0; q < 2; q++) {
                int e = q * 128 + t128;
                int r = e >> 5, cl = e & 31, c = qq * 32 + cl;
                float v = (cb[0 * 320 + r * LDC + cl] + cb[1 * 320 + r * LDC + cl])
                        + (cb[2 * 320 + r * LDC + cl] + cb[3 * 320 + r * LDC + cl])
                        + B2s[c];
                float h2 = tanh_fast(v);
                G2bf[r * LDA + c] = __float2bfloat16(W3s[c] * (1.0f - h2 * h2));
            }
        }
        __syncthreads();

        // ===== P3: g2 @ W2^T  (8x128, K=64): nt=pp, khalf=kh ================
        wmma::fill_fragment(fc, 0.0f);
        #pragma unroll
        for (int u = 0; u < 2; u++) {
            int kt = kh * 2 + u;
            wmma::load_matrix_sync(fa, G2bf + kt * 16, LDA);
            wmma::load_matrix_sync(fb, W2Ts + (kt * 16) * LDW1 + pp * 32, LDW1);
            wmma::mma_sync(fc, fa, fb, fc);
        }
        wmma::store_matrix_sync(CSw, fc, LDC, wmma::mem_row_major);
        asm volatile("bar.sync %0, %1;" :: "r"(1 + pp), "r"(64) : "memory");
        // E3 (pair): g1 = sum2 * (1 - h1^2) -> G1bf
        {
            const float* c0 = CSf + (2 * pp) * 320;
            const float* c1 = CSf + (2 * pp + 1) * 320;
            #pragma unroll
            for (int q = 0; q < 4; q++) {
                int e = q * 64 + t64;
                int r = e >> 5, cl = e & 31, c = pp * 32 + cl;
                float v = c0[r * LDC + cl] + c1[r * LDC + cl];
                float h1 = __bfloat162float(H1bf[r * LDH + c]);
                G1bf[r * LDH + c] = __float2bfloat16(v * (1.0f - h1 * h1));
            }
        }
        __syncthreads();

        // ===== P4: g1 @ W1^T  (8x64, K=128): nt=qq, kquarter=kq =============
        wmma::fill_fragment(fc, 0.0f);
        #pragma unroll
        for (int u = 0; u < 2; u++) {
            int kt = kq * 2 + u;
            wmma::load_matrix_sync(fa, G1bf + kt * 16, LDH);
            wmma::load_matrix_sync(fb, W1Ts + (kt * 16) * LDW2 + qq * 32, LDW2);
            wmma::mma_sync(fc, fa, fb, fc);
        }
        wmma::store_matrix_sync(CSw, fc, LDC, wmma::mem_row_major);
        asm volatile("bar.sync %0, %1;" :: "r"(5 + qq), "r"(128) : "memory");
        // E4 (quad): ynew = y - dy*h + sig*z*sqrt(h) -> Yf, Ybf, out
        {
            const float* cb = CSf + (qq * 4) * 320;
            #pragma unroll
            for (int q = 0; q < 2; q++) {
                int e = q * 128 + t128;
                int r = e >> 5, cl = e & 31, k = qq * 32 + cl;
                float dy = (cb[0 * 320 + r * LDC + cl] + cb[1 * 320 + r * LDC + cl])
                         + (cb[2 * 320 + r * LDC + cl] + cb[3 * 320 + r * LDC + cl]);
                int b = rowTop + r;
                float ynew = fmaf(-dy, hstep, Yf[r * 64 + k]) + zsc[q];
                Yf[r * 64 + k] = ynew;
                Ybf[r * LDA + k] = __float2bfloat16(ynew);
                out[((size_t)b * SS + (s + 1)) * HH + k] = ynew;
            }
        }
        __syncthreads();
    }
}

// ---------------------------------------------------------------------------
extern "C" void kernel_launch(void* const* d_in, const int* in_sizes, int n_in,
                              void* d_out, int out_size)
{
    (void)in_sizes; (void)n_in; (void)out_size;
    const float* ts    = (const float*)d_in[0];   // time_series (B,S,3)
    const float* noise = (const float*)d_in[1];   // (S-1,B,H)
    const float* Wp1   = (const float*)d_in[2];   // (65,128)
    const float* bp1   = (const float*)d_in[3];   // (128,)
    const float* Wp2   = (const float*)d_in[4];   // (128,64)
    const float* bp2   = (const float*)d_in[5];   // (64,)
    const float* Wp3   = (const float*)d_in[6];   // (64,1)
    // d_in[7] = bp3 (unused: constant shift, zero gradient)
    const float* Wd1   = (const float*)d_in[8];   // (1,32)
    const float* bd1   = (const float*)d_in[9];   // (32,)
    const float* Wd2   = (const float*)d_in[10];  // (32,64)
    const float* bd2   = (const float*)d_in[11];  // (64,)
    const float* mn    = (const float*)d_in[12];  // scalar
    const float* mx    = (const float*)d_in[13];  // scalar
    float* out = (float*)d_out;

    cudaFuncSetAttribute(sde_scan_kernel,
                         cudaFuncAttributeMaxDynamicSharedMemorySize, SMEM_BYTES);

    sigma_kernel<<<SM1, HH>>>(ts, Wd1, bd1, Wd2, bd2, mn, mx);
    sde_scan_kernel<<<BB / 8, 256, SMEM_BYTES>>>(ts, noise, Wp1, bp1, Wp2, bp2, Wp3, out);
}

// round 14
// speedup vs baseline: 1.2075x; 1.0327x over previous
#include <cuda_runtime.h>
#include <cuda_bf16.h>
#include <mma.h>
#include <cstdint>

using namespace nvcuda;

// Problem constants (LangevinSDEContiformer: B=1024, S=512, H=64, D_IN=3)
#define BB   1024
#define SS   512
#define HH   64
#define DIN  3
#define SM1  511    // S-1 steps

__device__ float d_sigsc[SM1 * HH];
__device__ float d_hstep[SM1];
__device__ float d_times[SM1];

__global__ void sigma_kernel(const float* __restrict__ ts,
                             const float* __restrict__ Wd1, const float* __restrict__ bd1,
                             const float* __restrict__ Wd2, const float* __restrict__ bd2,
                             const float* __restrict__ minp, const float* __restrict__ maxp)
{
    __shared__ float hh[32];
    int s = blockIdx.x;
    int tid = threadIdx.x;
    float t = ts[(size_t)s * DIN];
    if (tid < 32) hh[tid] = fmaxf(t * Wd1[tid] + bd1[tid], 0.0f);
    __syncthreads();
    float acc = bd2[tid];
    #pragma unroll
    for (int i = 0; i < 32; i++) acc += hh[i] * Wd2[i * HH + tid];
    float sp = fmaxf(acc, 0.0f) + log1pf(expf(-fabsf(acc)));
    float mind = fabsf(minp[0]);
    float maxd = fabsf(maxp[0]);
    float sig = fminf(fmaxf(sp + mind, mind), maxd);
    float hs = ts[(size_t)(s + 1) * DIN] - t;
    d_sigsc[s * HH + tid] = sig * sqrtf(hs);
    if (tid == 0) { d_hstep[s] = hs; d_times[s] = t; }
}

__device__ __forceinline__ float tanh_fast(float x) {
    float y;
    asm("tanh.approx.f32 %0, %1;" : "=f"(y) : "f"(x));
    return y;
}

// ---------------------------------------------------------------------------
// Tensor-core scan, TWO independent pipelines per CTA.
// 128 CTAs x 256 thr (8 warps). CTA owns 8 rows = 2 groups x (4 warps, 4 rows).
// Each group runs the full 4-phase step loop with ITS OWN named barriers
// (ids 1-2 group / 3-6 pair); NO __syncthreads in the loop -> groups drift,
// hiding each other's barrier stalls.  wmma m8n32k16 bf16->f32; m8 tiles
// carry 4 real rows (rows 4-7 zero; tensor pipe is ~5% busy, waste is free).
//   128-col phases (P1,P3): warp c owns n-tile c (32 cols), FULL K (4 mma),
//                           epilogue own-tile after __syncwarp.
//    64-col phases (P2,P4): 2 n-tiles x 2 k-halves, 64-thr pair barrier,
//                           pair epilogue.
// ---------------------------------------------------------------------------
#define LDW1  136     // W1s / W2Ts row stride (128 cols + 8 pad)
#define LDW2  72      // W2s / W1Ts row stride (64 cols + 8 pad)
#define LDA   72      // Y / G2 stride (64 + 8)
#define LDH   136     // H1 / G1 stride (128 + 8)
#define LDC   40      // C scratch row stride (f32)
// bf16 element offsets
#define OFF_W1S   0                       // [64][136]
#define OFF_W2S   (OFF_W1S  + 64*136)     // [128][72]
#define OFF_W2TS  (OFF_W2S  + 128*72)     // [64][136]
#define OFF_W1TS  (OFF_W2TS + 64*136)     // [128][72]
#define OFF_YBF   (OFF_W1TS + 128*72)     // [2][8][72]
#define OFF_H1BF  (OFF_YBF  + 2*8*72)     // [2][8][136]
#define OFF_G2BF  (OFF_H1BF + 2*8*136)    // [2][8][72]
#define OFF_G1BF  (OFF_G2BF + 2*8*72)     // [2][8][136]
#define BF16_ELEMS (OFF_G1BF + 2*8*136)   // 42496 (even)
// f32 offsets (units of f32)
#define F32_BASE  (BF16_ELEMS / 2)        // 21248
#define OFF_W1T   (F32_BASE)              // [128]
#define OFF_B1    (OFF_W1T + 128)         // [128]
#define OFF_B2    (OFF_B1 + 128)          // [64]
#define OFF_W3    (OFF_B2 + 64)           // [64]
#define OFF_YF    (OFF_W3 + 64)           // [2][4][64]
#define OFF_CS    (OFF_YF + 512)          // 8 warps x [8][40] = 2560
#define SMEM_FLOATS (OFF_CS + 2560)
#define SMEM_BYTES  (SMEM_FLOATS * 4)     // ~99 KB

__global__ void __launch_bounds__(256, 1)
sde_scan_kernel(const float* __restrict__ ts, const float* __restrict__ noise,
                const float* __restrict__ Wp1, const float* __restrict__ bp1,
                const float* __restrict__ Wp2, const float* __restrict__ bp2,
                const float* __restrict__ Wp3, float* __restrict__ out)
{
    extern __shared__ float smf[];
    __nv_bfloat16* bfb  = (__nv_bfloat16*)smf;
    __nv_bfloat16* W1s  = bfb + OFF_W1S;   // [64][136]  W1[k][j]
    __nv_bfloat16* W2s  = bfb + OFF_W2S;   // [128][72]  W2[k][j]
    __nv_bfloat16* W2Ts = bfb + OFF_W2TS;  // [64][136]  W2T[j][i]
    __nv_bfloat16* W1Ts = bfb + OFF_W1TS;  // [128][72]  W1T[i][k]
    float* W1t = smf + OFF_W1T;
    float* B1s = smf + OFF_B1;
    float* B2s = smf + OFF_B2;
    float* W3s = smf + OFF_W3;
    float* CSf = smf + OFF_CS;

    const int tid  = threadIdx.x;
    const int lane = tid & 31;
    const int w    = tid >> 5;            // warp 0..7
    const int g    = w >> 2;              // group 0/1 (4 rows each)
    const int c    = w & 3;               // warp role within group
    const int nt   = c & 1;               // n-tile for 64-col phases
    const int hp   = c >> 1;              // k-half / row-half for pair epilogue
    const int rowTop = blockIdx.x * 8;
    const int gbar = 1 + g;               // group barrier (128 thr)
    const int pbar = 3 + g * 2 + nt;      // pair barrier (64 thr)

    // per-group buffers
    __nv_bfloat16* Yg  = bfb + OFF_YBF  + g * 8 * LDA;
    __nv_bfloat16* H1g = bfb + OFF_H1BF + g * 8 * LDH;
    __nv_bfloat16* G2g = bfb + OFF_G2BF + g * 8 * LDA;
    __nv_bfloat16* G1g = bfb + OFF_G1BF + g * 8 * LDH;
    float* Yfg = smf + OFF_YF + g * 256;  // [4][64] fp32 master
    float* CSw = CSf + w * 320;           // own C tile [8][40]
    float* CSg = CSf + g * 4 * 320;       // group's 4 C tiles

    // ---- pack weights (bf16, 4 layouts) + consts
    for (int i = tid; i < 64 * 128; i += 256) {        // W1s[k][j]
        int k = i >> 7, j = i & 127;
        W1s[k * LDW1 + j] = __float2bfloat16(Wp1[i]);
    }
    for (int i = tid; i < 128 * 64; i += 256) {        // W2s[k][j]
        int k = i >> 6, j = i & 63;
        W2s[k * LDW2 + j] = __float2bfloat16(Wp2[i]);
    }
    for (int i = tid; i < 64 * 128; i += 256) {        // W2Ts[j][i2]
        int j = i >> 7, i2 = i & 127;
        W2Ts[j * LDW1 + i2] = __float2bfloat16(Wp2[i2 * 64 + j]);
    }
    for (int i = tid; i < 128 * 64; i += 256) {        // W1Ts[i2][k]
        int i2 = i >> 6, k = i & 63;
        W1Ts[i2 * LDW2 + k] = __float2bfloat16(Wp1[k * 128 + i2]);
    }
    if (tid < 128) { W1t[tid] = Wp1[64 * 128 + tid]; B1s[tid] = bp1[tid]; }
    if (tid < 64)  { B2s[tid] = bp2[tid]; W3s[tid] = Wp3[tid]; }

    // ---- zero all activation buffers (incl. padding rows 4-7)
    for (int i = tid; i < BF16_ELEMS - OFF_YBF; i += 256)
        bfb[OFF_YBF + i] = __float2bfloat16(0.0f);
    __syncthreads();

    // ---- init y0 (4 real rows per group) and write out[:,0,:]
    #pragma unroll
    for (int q = 0; q < 2; q++) {
        int e = q * 256 + tid;
        int k = e & 63, r8 = e >> 6;           // r8 = CTA row 0..7
        int gg = r8 >> 2, lr = r8 & 3;
        int b = rowTop + r8;
        float v = (k < DIN) ? ts[(size_t)b * SS * DIN + k] : 0.0f;
        smf[OFF_YF + gg * 256 + lr * 64 + k] = v;
        bfb[OFF_YBF + gg * 8 * LDA + lr * LDA + k] = __float2bfloat16(v);
        out[((size_t)b * SS) * HH + k] = v;
    }
    __syncthreads();

    wmma::fragment<wmma::matrix_a, 8, 32, 16, __nv_bfloat16, wmma::row_major> fa;
    wmma::fragment<wmma::matrix_b, 8, 32, 16, __nv_bfloat16, wmma::row_major> fb;
    wmma::fragment<wmma::accumulator, 8, 32, 16, float> fc;

    for (int s = 0; s < SM1; s++) {
        const float tcur  = d_times[s];
        const float hstep = d_hstep[s];

        // prefetch noise*sigma matching E4 mapping: rows hp*2+q, col nt*32+lane
        float zsc[2];
        #pragma unroll
        for (int q = 0; q < 2; q++) {
            int r = hp * 2 + q;
            int k = nt * 32 + lane;
            int b = rowTop + g * 4 + r;
            zsc[q] = d_sigsc[s * HH + k] * noise[((size_t)s * BB + b) * HH + k];
        }

        // ===== P1: [y] @ W1 (4x128, K=64). warp c owns n-tile c, full K =====
        wmma::fill_fragment(fc, 0.0f);
        #pragma unroll
        for (int kt = 0; kt < 4; kt++) {
            wmma::load_matrix_sync(fa, Yg + kt * 16, LDA);
            wmma::load_matrix_sync(fb, W1s + (kt * 16) * LDW1 + c * 32, LDW1);
            wmma::mma_sync(fc, fa, fb, fc);
        }
        wmma::store_matrix_sync(CSw, fc, LDC, wmma::mem_row_major);
        __syncwarp();
        // E1 own-tile: h1 = tanh(C + t*W1t + b1), rows 0-3, cols c*32+lane
        #pragma unroll
        for (int q = 0; q < 4; q++) {
            int col = c * 32 + lane;
            float v = CSw[q * LDC + lane] + fmaf(tcur, W1t[col], B1s[col]);
            H1g[q * LDH + col] = __float2bfloat16(tanh_fast(v));
        }
        asm volatile("bar.sync %0, %1;" :: "r"(gbar), "r"(128) : "memory");

        // ===== P2: h1 @ W2 (4x64, K=128). nt x k-half ========================
        wmma::fill_fragment(fc, 0.0f);
        #pragma unroll
        for (int u = 0; u < 4; u++) {
            int kt = hp * 4 + u;
            wmma::load_matrix_sync(fa, H1g + kt * 16, LDH);
            wmma::load_matrix_sync(fb, W2s + (kt * 16) * LDW2 + nt * 32, LDW2);
            wmma::mma_sync(fc, fa, fb, fc);
        }
        wmma::store_matrix_sync(CSw, fc, LDC, wmma::mem_row_major);
        asm volatile("bar.sync %0, %1;" :: "r"(pbar), "r"(64) : "memory");
        // E2 pair: g2 = W3*(1 - tanh(sum2 + b2)^2); rows hp*2..hp*2+1
        {
            const float* cs0 = CSg + nt * 320;
            const float* cs1 = CSg + (nt + 2) * 320;
            #pragma unroll
            for (int q = 0; q < 2; q++) {
                int r = hp * 2 + q;
                int col = nt * 32 + lane;
                float v = cs0[r * LDC + lane] + cs1[r * LDC + lane] + B2s[col];
                float h2 = tanh_fast(v);
                G2g[r * LDA + col] = __float2bfloat16(W3s[col] * (1.0f - h2 * h2));
            }
        }
        asm volatile("bar.sync %0, %1;" :: "r"(gbar), "r"(128) : "memory");

        // ===== P3: g2 @ W2^T (4x128, K=64). warp c owns n-tile c, full K ====
        wmma::fill_fragment(fc, 0.0f);
        #pragma unroll
        for (int kt = 0; kt < 4; kt++) {
            wmma::load_matrix_sync(fa, G2g + kt * 16, LDA);
            wmma::load_matrix_sync(fb, W2Ts + (kt * 16) * LDW1 + c * 32, LDW1);
            wmma::mma_sync(fc, fa, fb, fc);
        }
        wmma::store_matrix_sync(CSw, fc, LDC, wmma::mem_row_major);
        __syncwarp();
        // E3 own-tile: g1 = C * (1 - h1^2)
        #pragma unroll
        for (int q = 0; q < 4; q++) {
            int col = c * 32 + lane;
            float v = CSw[q * LDC + lane];
            float h1 = __bfloat162float(H1g[q * LDH + col]);
            G1g[q * LDH + col] = __float2bfloat16(v * (1.0f - h1 * h1));
        }
        asm volatile("bar.sync %0, %1;" :: "r"(gbar), "r"(128) : "memory");

        // ===== P4: g1 @ W1^T (4x64, K=128). nt x k-half ======================
        wmma::fill_fragment(fc, 0.0f);
        #pragma unroll
        for (int u = 0; u < 4; u++) {
            int kt = hp * 4 + u;
            wmma::load_matrix_sync(fa, G1g + kt * 16, LDH);
            wmma::load_matrix_sync(fb, W1Ts + (kt * 16) * LDW2 + nt * 32, LDW2);
            wmma::mma_sync(fc, fa, fb, fc);
        }
        wmma::store_matrix_sync(CSw, fc, LDC, wmma::mem_row_major);
        asm volatile("bar.sync %0, %1;" :: "r"(pbar), "r"(64) : "memory");
        // E4 pair: ynew = y - dy*h + sig*z*sqrt(h) -> Yfg, Yg, out
        {
            const float* cs0 = CSg + nt * 320;
            const float* cs1 = CSg + (nt + 2) * 320;
            #pragma unroll
            for (int q = 0; q < 2; q++) {
                int r = hp * 2 + q;
                int k = nt * 32 + lane;
                float dy = cs0[r * LDC + lane] + cs1[r * LDC + lane];
                int b = rowTop + g * 4 + r;
                float ynew = fmaf(-dy, hstep, Yfg[r * 64 + k]) + zsc[q];
                Yfg[r * 64 + k] = ynew;
                Yg[r * LDA + k] = __float2bfloat16(ynew);
                out[((size_t)b * SS + (s + 1)) * HH + k] = ynew;
            }
        }
        asm volatile("bar.sync %0, %1;" :: "r"(gbar), "r"(128) : "memory");
    }
}

// ---------------------------------------------------------------------------
extern "C" void kernel_launch(void* const* d_in, const int* in_sizes, int n_in,
                              void* d_out, int out_size)
{
    (void)in_sizes; (void)n_in; (void)out_size;
    const float* ts    = (const float*)d_in[0];   // time_series (B,S,3)
    const float* noise = (const float*)d_in[1];   // (S-1,B,H)
    const float* Wp1   = (const float*)d_in[2];   // (65,128)
    const float* bp1   = (const float*)d_in[3];   // (128,)
    const float* Wp2   = (const float*)d_in[4];   // (128,64)
    const float* bp2   = (const float*)d_in[5];   // (64,)
    const float* Wp3   = (const float*)d_in[6];   // (64,1)
    // d_in[7] = bp3 (unused: constant shift, zero gradient)
    const float* Wd1   = (const float*)d_in[8];   // (1,32)
    const float* bd1   = (const float*)d_in[9];   // (32,)
    const float* Wd2   = (const float*)d_in[10];  // (32,64)
    const float* bd2   = (const float*)d_in[11];  // (64,)
    const float* mn    = (const float*)d_in[12];  // scalar
    const float* mx    = (const float*)d_in[13];  // scalar
    float* out = (float*)d_out;

    cudaFuncSetAttribute(sde_scan_kernel,
                         cudaFuncAttributeMaxDynamicSharedMemorySize, SMEM_BYTES);

    sigma_kernel<<<SM1, HH>>>(ts, Wd1, bd1, Wd2, bd2, mn, mx);
    sde_scan_kernel<<<BB / 8, 256, SMEM_BYTES>>>(ts, noise, Wp1, bp1, Wp2, bp2, Wp3, out);
}

// round 15
// speedup vs baseline: 1.7048x; 1.4119x over previous
#include <cuda_runtime.h>
#include <cuda_bf16.h>
#include <cstdint>

// Problem constants (LangevinSDEContiformer: B=1024, S=512, H=64, D_IN=3)
#define BB   1024
#define SS   512
#define HH   64
#define DIN  3
#define SM1  511    // S-1 steps

__device__ float d_sigsc[SM1 * HH];
__device__ float d_hstep[SM1];
__device__ float d_times[SM1];

__global__ void sigma_kernel(const float* __restrict__ ts,
                             const float* __restrict__ Wd1, const float* __restrict__ bd1,
                             const float* __restrict__ Wd2, const float* __restrict__ bd2,
                             const float* __restrict__ minp, const float* __restrict__ maxp)
{
    __shared__ float hh[32];
    int s = blockIdx.x;
    int tid = threadIdx.x;
    float t = ts[(size_t)s * DIN];
    if (tid < 32) hh[tid] = fmaxf(t * Wd1[tid] + bd1[tid], 0.0f);
    __syncthreads();
    float acc = bd2[tid];
    #pragma unroll
    for (int i = 0; i < 32; i++) acc += hh[i] * Wd2[i * HH + tid];
    float sp = fmaxf(acc, 0.0f) + log1pf(expf(-fabsf(acc)));
    float mind = fabsf(minp[0]);
    float maxd = fabsf(maxp[0]);
    float sig = fminf(fmaxf(sp + mind, mind), maxd);
    float hs = ts[(size_t)(s + 1) * DIN] - t;
    d_sigsc[s * HH + tid] = sig * sqrtf(hs);
    if (tid == 0) { d_hstep[s] = hs; d_times[s] = t; }
}

typedef unsigned int u32;

__device__ __forceinline__ u32 packbf(float lo, float hi) {
    u32 r;
    asm("cvt.rn.bf16x2.f32 %0, %1, %2;" : "=r"(r) : "f"(hi), "f"(lo));
    return r;
}
__device__ __forceinline__ float tanh_fast(float x) {
    float y;
    asm("tanh.approx.f32 %0, %1;" : "=f"(y) : "f"(x));
    return y;
}
// mma.m16n8k16 row.col bf16 -> f32.  C layout (16x8):
//   c0:(row=lane/4, col=(lane%4)*2) c1:(.., col+1) c2:(row+8, col) c3:(row+8, col+1)
__device__ __forceinline__ void mma16816(float* c, uint4 a, u32 b0, u32 b1) {
    asm volatile(
        "mma.sync.aligned.m16n8k16.row.col.f32.bf16.bf16.f32 "
        "{%0,%1,%2,%3}, {%4,%5,%6,%7}, {%8,%9}, {%0,%1,%2,%3};"
        : "+f"(c[0]), "+f"(c[1]), "+f"(c[2]), "+f"(c[3])
        : "r"(a.x), "r"(a.y), "r"(a.z), "r"(a.w), "r"(b0), "r"(b1));
}

// ---------------------------------------------------------------------------
// Transposed tensor-core scan.  128 CTAs x 256 thr; 2 groups x (4 warps, 4 rows).
// C tiles = [16 out-features x 8 batch-rows] (rows 4..7 padding, noise=0).
// Every warp owns complete output features with FULL K each phase ->
// register-only epilogues, 4 group barriers per step, NO C scratch.
// A (weights) pre-swizzled into per-lane uint4 fragments (LDS.128).
// B (activations) stored as feature-pair-packed bf16x2 words [K/2][8 rows].
// ---------------------------------------------------------------------------
// smem (u32 units):
#define OFF_AF    0                        // 128 frags x 32 lanes x uint4 = 16384 u32
#define OFF_ACT   16384                    // per group 1536 u32: Y:256 H:512 G2:256 G1:512
#define ACT_G     1536
#define AOFF_Y    0
#define AOFF_H    256
#define AOFF_G2   768
#define AOFF_G1   1024
#define OFF_F32   (OFF_ACT + 2*ACT_G)      // 19456
#define OFF_W1T   (OFF_F32)                // [128] f32
#define OFF_B1    (OFF_W1T + 128)
#define OFF_B2    (OFF_B1 + 128)           // [64]
#define OFF_W3    (OFF_B2 + 64)            // [64]
#define OFF_YF    (OFF_W3 + 64)            // [2][64][8] f32 = 1024
#define SMEM_U32  (OFF_YF + 1024)          // 20864
#define SMEM_BYTES (SMEM_U32 * 4)          // 83456

__global__ void __launch_bounds__(256, 1)
sde_scan_kernel(const float* __restrict__ ts, const float* __restrict__ noise,
                const float* __restrict__ Wp1, const float* __restrict__ bp1,
                const float* __restrict__ Wp2, const float* __restrict__ bp2,
                const float* __restrict__ Wp3, float* __restrict__ out)
{
    extern __shared__ u32 smu[];
    uint4* AF = (uint4*)smu;               // [128 frags][32 lanes]
    float* W1t = (float*)(smu + OFF_W1T);
    float* B1s = (float*)(smu + OFF_B1);
    float* B2s = (float*)(smu + OFF_B2);
    float* W3s = (float*)(smu + OFF_W3);

    const int tid  = threadIdx.x;
    const int lane = tid & 31;
    const int w    = tid >> 5;
    const int g    = w >> 2;               // group 0/1
    const int c    = w & 3;                // warp role in group
    const int rowTop = blockIdx.x * 8;
    const int gbar = 1 + g;

    u32* ActY  = smu + OFF_ACT + g * ACT_G + AOFF_Y;   // [32 k2][8 r]
    u32* ActH  = smu + OFF_ACT + g * ACT_G + AOFF_H;   // [64][8]
    u32* ActG2 = smu + OFF_ACT + g * ACT_G + AOFF_G2;  // [32][8]
    u32* ActG1 = smu + OFF_ACT + g * ACT_G + AOFF_G1;  // [64][8]
    __nv_bfloat16* ActHb  = (__nv_bfloat16*)ActH;
    __nv_bfloat16* ActG2b = (__nv_bfloat16*)ActG2;
    __nv_bfloat16* ActG1b = (__nv_bfloat16*)ActG1;
    __nv_bfloat16* ActYb  = (__nv_bfloat16*)ActY;
    float* Yf = (float*)(smu + OFF_YF) + g * 512;      // [64 f][8 r]

    // ---- build weight A-fragments (128 frags). phase p: frag = p*32 + mt*KC + kc
    //  P1: A[m=j<128][k<64]   = Wp1[k*128+m]   (8 mt x 4 kc)
    //  P2: A[m=j2<64][k<128]  = Wp2[k*64+m]    (4 mt x 8 kc)
    //  P3: A[m=i<128][k=j2<64]= Wp2[m*64+k]    (8 mt x 4 kc)
    //  P4: A[m=k<64][k2=i<128]= Wp1[m*128+k2]  (4 mt x 8 kc)
    for (int fi = w; fi < 128; fi += 8) {
        int ph = fi >> 5, loc = fi & 31;
        int KC = (ph == 0 || ph == 2) ? 4 : 8;
        int mt = loc / KC, kc = loc % KC;
        int r0 = mt * 16 + (lane >> 2);
        int c0 = kc * 16 + (lane & 3) * 2;
        float v[2][4];   // [rhalf][0:c0,1:c0+1,2:c0+8,3:c0+9]
        #pragma unroll
        for (int rh = 0; rh < 2; rh++) {
            int m = r0 + rh * 8;
            #pragma unroll
            for (int cc = 0; cc < 4; cc++) {
                int k = c0 + (cc >> 1) * 8 + (cc & 1);
                float x;
                if (ph == 0)      x = Wp1[k * 128 + m];
                else if (ph == 1) x = Wp2[k * 64 + m];
                else if (ph == 2) x = Wp2[m * 64 + k];
                else              x = Wp1[m * 128 + k];
                v[rh][cc] = x;
            }
        }
        uint4 fr;
        fr.x = packbf(v[0][0], v[0][1]);   // (r0, c0,c0+1)
        fr.y = packbf(v[1][0], v[1][1]);   // (r0+8, c0,c0+1)
        fr.z = packbf(v[0][2], v[0][3]);   // (r0, c0+8,c0+9)
        fr.w = packbf(v[1][2], v[1][3]);   // (r0+8, ...)
        AF[fi * 32 + lane] = fr;
    }
    if (tid < 128) { W1t[tid] = Wp1[64 * 128 + tid]; B1s[tid] = bp1[tid]; }
    if (tid < 64)  { B2s[tid] = bp2[tid]; W3s[tid] = Wp3[tid]; }

    // ---- init ActY (bf16x2 pairs), Yf (fp32 master), out[:,0,:]
    for (int idx = tid; idx < 512; idx += 256) {       // ActY: 2 groups x 256 words
        int gg = idx >> 8, ww = idx & 255;
        int f2 = ww >> 3, r = ww & 7;
        float v0 = 0.f, v1 = 0.f;
        if (r < 4) {
            int b = rowTop + gg * 4 + r;
            if (2 * f2 < DIN)     v0 = ts[(size_t)b * SS * DIN + 2 * f2];
            if (2 * f2 + 1 < DIN) v1 = ts[(size_t)b * SS * DIN + 2 * f2 + 1];
        }
        smu[OFF_ACT + gg * ACT_G + AOFF_Y + ww] = packbf(v0, v1);
    }
    for (int idx = tid; idx < 1024; idx += 256) {      // Yf
        int gg = idx >> 9, ww = idx & 511;
        int f = ww >> 3, r = ww & 7;
        float v = 0.f;
        if (r < 4 && f < DIN) v = ts[(size_t)(rowTop + gg * 4 + r) * SS * DIN + f];
        ((float*)(smu + OFF_YF))[gg * 512 + ww] = v;
    }
    for (int idx = tid; idx < 512; idx += 256) {       // out step 0
        int r8 = idx >> 6, k = idx & 63;
        int b = rowTop + r8;
        out[((size_t)b * SS) * HH + k] = (k < DIN) ? ts[(size_t)b * SS * DIN + k] : 0.f;
    }
    __syncthreads();

    const int lq  = lane >> 2;            // 0..7 (feature sub-index)
    const int lr2 = (lane & 3) * 2;       // base batch row (0,2,4,6)

    for (int s = 0; s < SM1; s++) {
        const float tcur  = d_times[s];
        const float hstep = d_hstep[s];

        // prefetch noise*sigma for E4 positions (f = 16c + lq + 8*(q>>1), r = lr2 + (q&1))
        float zsc[4];
        #pragma unroll
        for (int q = 0; q < 4; q++) {
            int f = 16 * c + lq + 8 * (q >> 1);
            int r = lr2 + (q & 1);
            zsc[q] = (r < 4)
                ? d_sigsc[s * HH + f] * noise[((size_t)s * BB + rowTop + g * 4 + r) * HH + f]
                : 0.f;
        }

        float h1v[8];

        // ===== P1: out j (128) = W1^T @ y. warp c: m-tiles {2c,2c+1}, K=64 ===
        {
            u32 by[8];
            #pragma unroll
            for (int kc = 0; kc < 4; kc++) {
                int k2 = kc * 8 + (lane & 3);
                by[2 * kc]     = ActY[k2 * 8 + lq];
                by[2 * kc + 1] = ActY[(k2 + 4) * 8 + lq];
            }
            #pragma unroll
            for (int t = 0; t < 2; t++) {
                float cc[4] = {0.f, 0.f, 0.f, 0.f};
                #pragma unroll
                for (int kc = 0; kc < 4; kc++)
                    mma16816(cc, AF[(0 * 32 + (2 * c + t) * 4 + kc) * 32 + lane],
                             by[2 * kc], by[2 * kc + 1]);
                #pragma unroll
                for (int q = 0; q < 4; q++) {
                    int f = 32 * c + 16 * t + lq + 8 * (q >> 1);
                    int r = lr2 + (q & 1);
                    float v = cc[q] + fmaf(tcur, W1t[f], B1s[f]);
                    float h = tanh_fast(v);
                    h1v[t * 4 + q] = h;
                    ActHb[(f >> 1) * 16 + r * 2 + (f & 1)] = __float2bfloat16(h);
                }
            }
        }
        asm volatile("bar.sync %0, %1;" :: "r"(gbar), "r"(128) : "memory");

        // ===== P2: out j2 (64) = W2^T @ h1. warp c: m-tile c, K=128 =========
        {
            u32 bh[16];
            #pragma unroll
            for (int kc = 0; kc < 8; kc++) {
                int k2 = kc * 8 + (lane & 3);
                bh[2 * kc]     = ActH[k2 * 8 + lq];
                bh[2 * kc + 1] = ActH[(k2 + 4) * 8 + lq];
            }
            float ce[4] = {0.f, 0.f, 0.f, 0.f}, co[4] = {0.f, 0.f, 0.f, 0.f};
            #pragma unroll
            for (int u = 0; u < 4; u++)
                mma16816(ce, AF[(32 + c * 8 + u) * 32 + lane], bh[2 * u], bh[2 * u + 1]);
            #pragma unroll
            for (int u = 4; u < 8; u++)
                mma16816(co, AF[(32 + c * 8 + u) * 32 + lane], bh[2 * u], bh[2 * u + 1]);
            #pragma unroll
            for (int q = 0; q < 4; q++) {
                int f = 16 * c + lq + 8 * (q >> 1);
                int r = lr2 + (q & 1);
                float h2 = tanh_fast(ce[q] + co[q] + B2s[f]);
                float g2 = W3s[f] * (1.0f - h2 * h2);
                ActG2b[(f >> 1) * 16 + r * 2 + (f & 1)] = __float2bfloat16(g2);
            }
        }
        asm volatile("bar.sync %0, %1;" :: "r"(gbar), "r"(128) : "memory");

        // ===== P3: out i (128) = W2 @ g2. warp c: m-tiles {2c,2c+1}, K=64 ===
        {
            u32 bg[8];
            #pragma unroll
            for (int kc = 0; kc < 4; kc++) {
                int k2 = kc * 8 + (lane & 3);
                bg[2 * kc]     = ActG2[k2 * 8 + lq];
                bg[2 * kc + 1] = ActG2[(k2 + 4) * 8 + lq];
            }
            #pragma unroll
            for (int t = 0; t < 2; t++) {
                float cc[4] = {0.f, 0.f, 0.f, 0.f};
                #pragma unroll
                for (int kc = 0; kc < 4; kc++)
                    mma16816(cc, AF[(64 + (2 * c + t) * 4 + kc) * 32 + lane],
                             bg[2 * kc], bg[2 * kc + 1]);
                #pragma unroll
                for (int q = 0; q < 4; q++) {
                    int f = 32 * c + 16 * t + lq + 8 * (q >> 1);
                    int r = lr2 + (q & 1);
                    float h1 = h1v[t * 4 + q];
                    float g1 = cc[q] * (1.0f - h1 * h1);
                    ActG1b[(f >> 1) * 16 + r * 2 + (f & 1)] = __float2bfloat16(g1);
                }
            }
        }
        asm volatile("bar.sync %0, %1;" :: "r"(gbar), "r"(128) : "memory");

        // ===== P4: dy k (64) = W1 @ g1. warp c: m-tile c, K=128; update y ===
        {
            u32 bg[16];
            #pragma unroll
            for (int kc = 0; kc < 8; kc++) {
                int k2 = kc * 8 + (lane & 3);
                bg[2 * kc]     = ActG1[k2 * 8 + lq];
                bg[2 * kc + 1] = ActG1[(k2 + 4) * 8 + lq];
            }
            float ce[4] = {0.f, 0.f, 0.f, 0.f}, co[4] = {0.f, 0.f, 0.f, 0.f};
            #pragma unroll
            for (int u = 0; u < 4; u++)
                mma16816(ce, AF[(96 + c * 8 + u) * 32 + lane], bg[2 * u], bg[2 * u + 1]);
            #pragma unroll
            for (int u = 4; u < 8; u++)
                mma16816(co, AF[(96 + c * 8 + u) * 32 + lane], bg[2 * u], bg[2 * u + 1]);
            #pragma unroll
            for (int q = 0; q < 4; q++) {
                int f = 16 * c + lq + 8 * (q >> 1);
                int r = lr2 + (q & 1);
                float dy = ce[q] + co[q];
                float ynew = fmaf(-dy, hstep, Yf[f * 8 + r]) + zsc[q];
                Yf[f * 8 + r] = ynew;
                ActYb[(f >> 1) * 16 + r * 2 + (f & 1)] = __float2bfloat16(ynew);
                if (r < 4)
                    out[((size_t)(rowTop + g * 4 + r) * SS + (s + 1)) * HH + f] = ynew;
            }
        }
        asm volatile("bar.sync %0, %1;" :: "r"(gbar), "r"(128) : "memory");
    }
}

// ---------------------------------------------------------------------------
extern "C" void kernel_launch(void* const* d_in, const int* in_sizes, int n_in,
                              void* d_out, int out_size)
{
    (void)in_sizes; (void)n_in; (void)out_size;
    const float* ts    = (const float*)d_in[0];   // time_series (B,S,3)
    const float* noise = (const float*)d_in[1];   // (S-1,B,H)
    const float* Wp1   = (const float*)d_in[2];   // (65,128)
    const float* bp1   = (const float*)d_in[3];   // (128,)
    const float* Wp2   = (const float*)d_in[4];   // (128,64)
    const float* bp2   = (const float*)d_in[5];   // (64,)
    const float* Wp3   = (const float*)d_in[6];   // (64,1)
    // d_in[7] = bp3 (unused: constant shift, zero gradient)
    const float* Wd1   = (const float*)d_in[8];   // (1,32)
    const float* bd1   = (const float*)d_in[9];   // (32,)
    const float* Wd2   = (const float*)d_in[10];  // (32,64)
    const float* bd2   = (const float*)d_in[11];  // (64,)
    const float* mn    = (const float*)d_in[12];  // scalar
    const float* mx    = (const float*)d_in[13];  // scalar
    float* out = (float*)d_out;

    cudaFuncSetAttribute(sde_scan_kernel,
                         cudaFuncAttributeMaxDynamicSharedMemorySize, SMEM_BYTES);

    sigma_kernel<<<SM1, HH>>>(ts, Wd1, bd1, Wd2, bd2, mn, mx);
    sde_scan_kernel<<<BB / 8, 256, SMEM_BYTES>>>(ts, noise, Wp1, bp1, Wp2, bp2, Wp3, out);
}